// round 1
// baseline (speedup 1.0000x reference)
#include <cuda_runtime.h>
#include <cuda_bf16.h>
#include <cstdint>
#include <cstddef>

// ---------------- problem constants ----------------
#define T_SEQ 2048
#define DIM   2048
#define NH    16
#define HD    128
#define FFN   8192
#define EPS_F 1.1920929e-07f
#define NEG_INF_F (-1e30f)

// ---------------- scratch (device globals; no allocs allowed) ----------------
__device__ float g_xn  [(size_t)T_SEQ * DIM];       // rmsnorm output (reused)
__device__ float g_qkv [(size_t)T_SEQ * 3 * DIM];   // [T, 48, 128]
__device__ float g_krot[(size_t)T_SEQ * NH * HD];   // rotated k before shift
__device__ float g_y   [(size_t)T_SEQ * DIM];       // attention output (gated)
__device__ float g_x1  [(size_t)T_SEQ * DIM];       // x + attn_out
__device__ float g_h   [(size_t)T_SEQ * FFN];       // MLP hidden
__device__ float g_agate[(size_t)T_SEQ * NH];
__device__ float g_vgate[(size_t)T_SEQ * NH];

// ---------------- RMSNorm over rows of length DIM ----------------
__global__ void __launch_bounds__(256) rmsnorm_kernel(const float* __restrict__ in,
                                                      float* __restrict__ outp) {
    int t = blockIdx.x;
    const float* r = in + (size_t)t * DIM;
    float ss = 0.f;
    for (int i = threadIdx.x; i < DIM; i += 256) { float v = r[i]; ss += v * v; }
    // block reduce
    __shared__ float sred[8];
    for (int o = 16; o; o >>= 1) ss += __shfl_xor_sync(0xffffffffu, ss, o);
    if ((threadIdx.x & 31) == 0) sred[threadIdx.x >> 5] = ss;
    __syncthreads();
    float tot = 0.f;
    #pragma unroll
    for (int i = 0; i < 8; i++) tot += sred[i];
    float scale = rsqrtf(tot / (float)DIM + EPS_F);
    for (int i = threadIdx.x; i < DIM; i += 256)
        outp[(size_t)t * DIM + i] = r[i] * scale;
}

// ---------------- generic tiled SGEMM ----------------
// C[M,N] = epi( alpha * A[M,K] @ op(B) )
// BTRANS=true : B given row-major [N,K]  (C = A B^T)
// BTRANS=false: B given row-major [K,N]  (C = A B)
// EPI: 0=none, 1=relu^2, 2=add addsrc
template<bool BTRANS, int EPI>
__global__ void __launch_bounds__(256) gemm_kernel(
    const float* __restrict__ A, const float* __restrict__ B,
    float* __restrict__ C, const float* __restrict__ addsrc,
    const float* __restrict__ alpha_ptr, int alpha_idx,
    int M, int N, int K)
{
    __shared__ float As[16][128];
    __shared__ float Bs[16][128];
    int tid = threadIdx.x;
    int bm = blockIdx.y, bn = blockIdx.x;
    int row0 = (tid >> 4) * 8, col0 = (tid & 15) * 8;
    float acc[8][8] = {};
    const float* Ab = A + (size_t)bm * 128 * K;

    for (int kt = 0; kt < K; kt += 16) {
        #pragma unroll
        for (int l = 0; l < 2; l++) {
            int id = tid + l * 256;
            int ar = id >> 2;
            int ac = (id & 3) * 4;
            float4 f = *(const float4*)(Ab + (size_t)ar * K + kt + ac);
            As[ac + 0][ar] = f.x; As[ac + 1][ar] = f.y;
            As[ac + 2][ar] = f.z; As[ac + 3][ar] = f.w;
        }
        if (BTRANS) {
            const float* Bb = B + (size_t)bn * 128 * K;
            #pragma unroll
            for (int l = 0; l < 2; l++) {
                int id = tid + l * 256;
                int br = id >> 2;
                int bc = (id & 3) * 4;
                float4 f = *(const float4*)(Bb + (size_t)br * K + kt + bc);
                Bs[bc + 0][br] = f.x; Bs[bc + 1][br] = f.y;
                Bs[bc + 2][br] = f.z; Bs[bc + 3][br] = f.w;
            }
        } else {
            #pragma unroll
            for (int l = 0; l < 2; l++) {
                int id = tid + l * 256;
                int br = id >> 5;
                int bc = (id & 31) * 4;
                float4 f = *(const float4*)(B + (size_t)(kt + br) * N + (size_t)bn * 128 + bc);
                *(float4*)&Bs[br][bc] = f;
            }
        }
        __syncthreads();
        #pragma unroll
        for (int kk = 0; kk < 16; kk++) {
            float a[8], b[8];
            #pragma unroll
            for (int i = 0; i < 8; i++) a[i] = As[kk][row0 + i];
            #pragma unroll
            for (int j = 0; j < 8; j++) b[j] = Bs[kk][col0 + j];
            #pragma unroll
            for (int i = 0; i < 8; i++)
                #pragma unroll
                for (int j = 0; j < 8; j++)
                    acc[i][j] = fmaf(a[i], b[j], acc[i][j]);
        }
        __syncthreads();
    }

    float alpha = alpha_ptr ? alpha_ptr[alpha_idx] : 1.0f;
    int crow = bm * 128 + row0, ccol = bn * 128 + col0;
    #pragma unroll
    for (int i = 0; i < 8; i++) {
        #pragma unroll
        for (int j = 0; j < 8; j++) {
            float v = alpha * acc[i][j];
            size_t idx = (size_t)(crow + i) * N + ccol + j;
            if (EPI == 1) { v = fmaxf(v, 0.f); v = v * v; }
            else if (EPI == 2) { v += addsrc[idx]; }
            C[idx] = v;
        }
    }
}

// ---------------- per-(t, head-slot) QK rmsnorm + rotary ----------------
// head-slot 0..15 = q (in place), 16..31 = k -> g_krot
__global__ void __launch_bounds__(128) qkrot_kernel(
    float* __restrict__ qkv, float* __restrict__ krot,
    const float* __restrict__ cosb, const float* __restrict__ sinb)
{
    int hs = blockIdx.x;   // 0..31
    int t  = blockIdx.y;
    int d  = threadIdx.x;  // 0..127
    float v = qkv[((size_t)t * 48 + hs) * HD + d];
    __shared__ float sm[HD];
    __shared__ float red[4];
    float ss = v * v;
    for (int o = 16; o; o >>= 1) ss += __shfl_xor_sync(0xffffffffu, ss, o);
    if ((d & 31) == 0) red[d >> 5] = ss;
    __syncthreads();
    float tot = red[0] + red[1] + red[2] + red[3];
    float n = v * rsqrtf(tot / (float)HD + EPS_F);
    sm[d] = n;
    __syncthreads();
    float o;
    if (d < 64) {
        float c = cosb[t * 64 + d], s = sinb[t * 64 + d];
        o = sm[d] * c + sm[d + 64] * s;
    } else {
        float c = cosb[t * 64 + d - 64], s = sinb[t * 64 + d - 64];
        o = -sm[d - 64] * s + sm[d] * c;
    }
    if (hs < 16) qkv[((size_t)t * 48 + hs) * HD + d] = o;
    else         krot[((size_t)t * NH + (hs - 16)) * HD + d] = o;
}

// ---------------- key-offset shift: g_krot -> qkv k-region ----------------
__global__ void __launch_bounds__(256) kshift_kernel(
    const float* __restrict__ krot, float* __restrict__ qkv,
    const int* __restrict__ key_offset)
{
    int idx = blockIdx.x * 256 + threadIdx.x;   // < T*NH*HD
    int d = idx & 127;
    int h = (idx >> 7) & 15;
    int t = idx >> 11;
    int ko = key_offset[0];
    bool up = (d >= 32 && d < 64) || (d >= 96);
    int st = (ko && up && t > 0) ? (t - 1) : t;
    qkv[((size_t)t * 48 + 16 + h) * HD + d] = krot[((size_t)st * NH + h) * HD + d];
}

// ---------------- gate logits: sigmoid(xn @ W^T) for attn + ve gates ----------------
__global__ void __launch_bounds__(256) gates_kernel(
    const float* __restrict__ xn, const float* __restrict__ agw,
    const float* __restrict__ vgw, float* __restrict__ agate,
    float* __restrict__ vgate)
{
    int t = blockIdx.x;
    int w = threadIdx.x >> 5, lane = threadIdx.x & 31;
    const float* xr = xn + (size_t)t * DIM;
    float acc[4] = {};
    const float* wbase[4];
    #pragma unroll
    for (int q = 0; q < 4; q++) {
        int o = w * 4 + q;
        wbase[q] = (o < 16) ? (agw + (size_t)o * DIM) : (vgw + (size_t)(o - 16) * DIM);
    }
    for (int dd = lane; dd < DIM; dd += 32) {
        float xv = xr[dd];
        #pragma unroll
        for (int q = 0; q < 4; q++) acc[q] = fmaf(xv, wbase[q][dd], acc[q]);
    }
    #pragma unroll
    for (int q = 0; q < 4; q++)
        for (int o2 = 16; o2; o2 >>= 1) acc[q] += __shfl_xor_sync(0xffffffffu, acc[q], o2);
    if (lane == 0) {
        #pragma unroll
        for (int q = 0; q < 4; q++) {
            int o = w * 4 + q;
            float g = 1.f / (1.f + expf(-acc[q]));
            if (o < 16) agate[t * NH + o] = g;
            else        vgate[t * NH + (o - 16)] = g;
        }
    }
}

// ---------------- v += sigmoid(ve_gate) * ve ----------------
__global__ void __launch_bounds__(256) vupdate_kernel(
    float* __restrict__ qkv, const float* __restrict__ ve,
    const float* __restrict__ vgate)
{
    int idx = blockIdx.x * 256 + threadIdx.x;   // < T*DIM
    int d = idx & 127;
    int h = (idx >> 7) & 15;
    int t = idx >> 11;
    float g = vgate[t * NH + h];
    qkv[((size_t)t * 48 + 32 + h) * HD + d] += g * ve[idx];
}

// ---------------- flash attention (fp32, doc + causal mask, gated epilogue) ----------------
// grid: (T/64, NH); 256 threads; dynamic smem 120 KB
#define F_QT 0
#define F_KT 8192
#define F_VS 16384
#define F_PT 24576
#define F_RED 28672
#define F_M  29696
#define F_L  29760
#define F_AL 29824
#define F_KD 29888
#define F_QD 29952
#define F_TOTAL 30016
#define FLASH_SMEM_BYTES (F_TOTAL * 4)

__global__ void __launch_bounds__(256) flash_kernel(
    const float* __restrict__ qkv, const int* __restrict__ docs,
    const float* __restrict__ attn_scale, const float* __restrict__ agate,
    float* __restrict__ y)
{
    extern __shared__ float fsm[];
    float* Qt   = fsm + F_QT;    // [128][64] transposed
    float* Kt   = fsm + F_KT;    // [128][64] transposed
    float* Vs   = fsm + F_VS;    // [64][128]
    float* Pt   = fsm + F_PT;    // [64(col)][64(row)]
    float* red  = fsm + F_RED;   // [64][16]
    float* mrow = fsm + F_M;
    float* lrow = fsm + F_L;
    float* arow = fsm + F_AL;
    int*   kd   = (int*)(fsm + F_KD);
    int*   qd   = (int*)(fsm + F_QD);

    int tid = threadIdx.x;
    int h  = blockIdx.y;
    int qi = blockIdx.x;
    int qbase = qi * 64;
    int ty = tid >> 4, tx = tid & 15;
    int row0 = ty * 4;
    float scale = attn_scale[0];

    // load Q tile (already rotated, in place in qkv heads 0..15), transposed
    #pragma unroll
    for (int l = 0; l < 8; l++) {
        int id = tid + l * 256;         // 0..2047
        int r = id >> 5;
        int c = (id & 31) * 4;
        float4 f = *(const float4*)&qkv[((size_t)(qbase + r) * 48 + h) * HD + c];
        Qt[(c + 0) * 64 + r] = f.x; Qt[(c + 1) * 64 + r] = f.y;
        Qt[(c + 2) * 64 + r] = f.z; Qt[(c + 3) * 64 + r] = f.w;
    }
    if (tid < 64) {
        qd[tid]   = docs[qbase + tid];
        mrow[tid] = NEG_INF_F;
        lrow[tid] = 0.f;
    }
    float o[4][8] = {};
    __syncthreads();

    for (int kb = 0; kb <= qi; kb++) {
        int kbase = kb * 64;
        #pragma unroll
        for (int l = 0; l < 8; l++) {
            int id = tid + l * 256;
            int r = id >> 5;
            int c = (id & 31) * 4;
            float4 f = *(const float4*)&qkv[((size_t)(kbase + r) * 48 + 16 + h) * HD + c];
            Kt[(c + 0) * 64 + r] = f.x; Kt[(c + 1) * 64 + r] = f.y;
            Kt[(c + 2) * 64 + r] = f.z; Kt[(c + 3) * 64 + r] = f.w;
            float4 g = *(const float4*)&qkv[((size_t)(kbase + r) * 48 + 32 + h) * HD + c];
            *(float4*)&Vs[r * 128 + c] = g;
        }
        if (tid < 64) kd[tid] = docs[kbase + tid];
        __syncthreads();

        // S = Q K^T (64x64), each thread a 4x4 subtile
        float s[4][4] = {};
        for (int d = 0; d < HD; d++) {
            float a[4], b[4];
            #pragma unroll
            for (int i = 0; i < 4; i++) a[i] = Qt[d * 64 + row0 + i];
            #pragma unroll
            for (int j = 0; j < 4; j++) b[j] = Kt[d * 64 + tx * 4 + j];
            #pragma unroll
            for (int i = 0; i < 4; i++)
                #pragma unroll
                for (int j = 0; j < 4; j++)
                    s[i][j] = fmaf(a[i], b[j], s[i][j]);
        }
        // scale + mask + per-thread rowmax
        #pragma unroll
        for (int i = 0; i < 4; i++) {
            int tg = qbase + row0 + i;
            int dq = qd[row0 + i];
            float mx = NEG_INF_F;
            #pragma unroll
            for (int j = 0; j < 4; j++) {
                int sg = kbase + tx * 4 + j;
                float v = s[i][j] * scale;
                bool valid = (sg <= tg) && (kd[tx * 4 + j] == dq);
                v = valid ? v : NEG_INF_F;
                s[i][j] = v;
                mx = fmaxf(mx, v);
            }
            red[(row0 + i) * 16 + tx] = mx;
        }
        __syncthreads();
        if (tid < 64) {
            float mx = red[tid * 16];
            #pragma unroll
            for (int j = 1; j < 16; j++) mx = fmaxf(mx, red[tid * 16 + j]);
            float mo = mrow[tid];
            float mn = fmaxf(mo, mx);
            mrow[tid] = mn;
            arow[tid] = expf(mo - mn);
        }
        __syncthreads();
        // rescale O, compute P, partial row sums
        #pragma unroll
        for (int i = 0; i < 4; i++) {
            float al = arow[row0 + i];
            #pragma unroll
            for (int j = 0; j < 8; j++) o[i][j] *= al;
        }
        #pragma unroll
        for (int i = 0; i < 4; i++) {
            float mn = mrow[row0 + i];
            float sum = 0.f;
            #pragma unroll
            for (int j = 0; j < 4; j++) {
                float v = s[i][j];
                float p = (v > -1e29f) ? expf(v - mn) : 0.f;
                Pt[(tx * 4 + j) * 64 + row0 + i] = p;
                sum += p;
            }
            red[(row0 + i) * 16 + tx] = sum;
        }
        __syncthreads();
        if (tid < 64) {
            float sm = 0.f;
            #pragma unroll
            for (int j = 0; j < 16; j++) sm += red[tid * 16 + j];
            lrow[tid] = lrow[tid] * arow[tid] + sm;
        }
        // O += P @ V
        #pragma unroll 8
        for (int kk = 0; kk < 64; kk++) {
            float p[4];
            #pragma unroll
            for (int i = 0; i < 4; i++) p[i] = Pt[kk * 64 + row0 + i];
            float4 v0 = *(float4*)&Vs[kk * 128 + tx * 8];
            float4 v1 = *(float4*)&Vs[kk * 128 + tx * 8 + 4];
            float vb[8] = {v0.x, v0.y, v0.z, v0.w, v1.x, v1.y, v1.z, v1.w};
            #pragma unroll
            for (int i = 0; i < 4; i++)
                #pragma unroll
                for (int j = 0; j < 8; j++)
                    o[i][j] = fmaf(p[i], vb[j], o[i][j]);
        }
        __syncthreads();
    }

    // epilogue: normalize + attn gate
    #pragma unroll
    for (int i = 0; i < 4; i++) {
        int t = qbase + row0 + i;
        float f = (1.0f / lrow[row0 + i]) * agate[t * NH + h];
        #pragma unroll
        for (int j = 0; j < 8; j++)
            y[(size_t)t * DIM + h * HD + tx * 8 + j] = o[i][j] * f;
    }
}

// ---------------- launch ----------------
extern "C" void kernel_launch(void* const* d_in, const int* in_sizes, int n_in,
                              void* d_out, int out_size) {
    const float* x           = (const float*)d_in[0];
    const float* ve          = (const float*)d_in[1];
    const float* qkvo_w      = (const float*)d_in[2];
    const float* attn_gate_w = (const float*)d_in[3];
    const float* ve_gate_w   = (const float*)d_in[4];
    const float* c_fc        = (const float*)d_in[5];
    const float* c_proj      = (const float*)d_in[6];
    const float* sa_lambdas  = (const float*)d_in[7];
    const float* cosb        = (const float*)d_in[8];
    const float* sinb        = (const float*)d_in[9];
    const float* attn_scale  = (const float*)d_in[10];
    const int*   docs        = (const int*)d_in[11];
    const int*   key_offset  = (const int*)d_in[12];
    float*       out         = (float*)d_out;

    float *xn, *qkv, *krot, *y, *x1, *hbuf, *agate, *vgate;
    cudaGetSymbolAddress((void**)&xn,    g_xn);
    cudaGetSymbolAddress((void**)&qkv,   g_qkv);
    cudaGetSymbolAddress((void**)&krot,  g_krot);
    cudaGetSymbolAddress((void**)&y,     g_y);
    cudaGetSymbolAddress((void**)&x1,    g_x1);
    cudaGetSymbolAddress((void**)&hbuf,  g_h);
    cudaGetSymbolAddress((void**)&agate, g_agate);
    cudaGetSymbolAddress((void**)&vgate, g_vgate);

    cudaFuncSetAttribute(flash_kernel,
                         cudaFuncAttributeMaxDynamicSharedMemorySize,
                         FLASH_SMEM_BYTES);

    // 1. xn = rmsnorm(x)
    rmsnorm_kernel<<<T_SEQ, 256>>>(x, xn);
    // 2. qkv = lam0 * xn @ Wqkv^T   (M=2048, N=6144, K=2048)
    gemm_kernel<true, 0><<<dim3(3 * DIM / 128, T_SEQ / 128), 256>>>(
        xn, qkvo_w, qkv, nullptr, sa_lambdas, 0, T_SEQ, 3 * DIM, DIM);
    // 3. per-head rmsnorm + rotary for q (in place) and k (-> krot)
    qkrot_kernel<<<dim3(32, T_SEQ), 128>>>(qkv, krot, cosb, sinb);
    // 4. key-offset shift: krot -> qkv k region
    kshift_kernel<<<(T_SEQ * NH * HD) / 256, 256>>>(krot, qkv, key_offset);
    // 5. attn + ve gate logits
    gates_kernel<<<T_SEQ, 256>>>(xn, attn_gate_w, ve_gate_w, agate, vgate);
    // 6. v += ve_gate * ve
    vupdate_kernel<<<(T_SEQ * DIM) / 256, 256>>>(qkv, ve, vgate);
    // 7. flash attention (gated epilogue) -> y
    flash_kernel<<<dim3(T_SEQ / 64, NH), 256, FLASH_SMEM_BYTES>>>(
        qkv, docs, attn_scale, agate, y);
    // 8. x1 = x + lam1 * y @ Wo^T
    gemm_kernel<true, 2><<<dim3(DIM / 128, T_SEQ / 128), 256>>>(
        y, qkvo_w + (size_t)3 * DIM * DIM, x1, x, sa_lambdas, 1, T_SEQ, DIM, DIM);
    // 9. xn = rmsnorm(x1)
    rmsnorm_kernel<<<T_SEQ, 256>>>(x1, xn);
    // 10. h = relu(xn @ c_fc^T)^2   (N=8192)
    gemm_kernel<true, 1><<<dim3(FFN / 128, T_SEQ / 128), 256>>>(
        xn, c_fc, hbuf, nullptr, nullptr, 0, T_SEQ, FFN, DIM);
    // 11. out = x1 + h @ c_proj     (K=8192, B not transposed)
    gemm_kernel<false, 2><<<dim3(DIM / 128, T_SEQ / 128), 256>>>(
        hbuf, c_proj, out, x1, nullptr, 0, T_SEQ, DIM, FFN);
}

// round 3
// speedup vs baseline: 2.3234x; 2.3234x over previous
#include <cuda_runtime.h>
#include <cuda_bf16.h>
#include <cstdint>
#include <cstddef>

// ---------------- problem constants ----------------
#define T_SEQ 2048
#define DIM   2048
#define NH    16
#define HD    128
#define FFN   8192
#define EPS_F 1.1920929e-07f
#define NEG_INF_F (-1e30f)

// ---------------- scratch (device globals; no runtime allocs) ----------------
__device__ float g_xn  [(size_t)T_SEQ * DIM];
__device__ float g_qkv [(size_t)T_SEQ * 3 * DIM];
__device__ float g_krot[(size_t)T_SEQ * NH * HD];
__device__ float g_y   [(size_t)T_SEQ * DIM];
__device__ float g_x1  [(size_t)T_SEQ * DIM];
__device__ float g_h   [(size_t)T_SEQ * FFN];
__device__ float g_agate[(size_t)T_SEQ * NH];
__device__ float g_vgate[(size_t)T_SEQ * NH];
__device__ float g_wqkv[(size_t)4 * DIM * DIM];   // tf32-rounded qkvo weights
__device__ float g_wfc [(size_t)FFN * DIM];       // tf32-rounded c_fc
__device__ float g_wpT [(size_t)DIM * FFN];       // tf32-rounded c_proj^T [DIM, FFN]

// ---------------- helpers ----------------
__device__ __forceinline__ float to_tf32(float x) {
    asm("cvt.rna.tf32.f32 %0, %1;" : "=f"(x) : "f"(x));
    return x;
}
__device__ __forceinline__ void cp_async16(uint32_t dst, const float* src) {
    asm volatile("cp.async.cg.shared.global [%0], [%1], 16;" :: "r"(dst), "l"(src));
}
__device__ __forceinline__ void cp_async_commit() {
    asm volatile("cp.async.commit_group;" ::: "memory");
}
template<int N>
__device__ __forceinline__ void cp_async_wait() {
    asm volatile("cp.async.wait_group %0;" :: "n"(N) : "memory");
}
__device__ __forceinline__ uint32_t smem_u32(const void* p) {
    uint32_t a;
    asm("{ .reg .u64 t; cvta.to.shared.u64 t, %1; cvt.u32.u64 %0, t; }" : "=r"(a) : "l"(p));
    return a;
}
__device__ __forceinline__ void mma_tf32(float& c0, float& c1, float& c2, float& c3,
                                         uint32_t a0, uint32_t a1, uint32_t a2, uint32_t a3,
                                         uint32_t b0, uint32_t b1) {
    asm volatile("mma.sync.aligned.m16n8k8.row.col.f32.tf32.tf32.f32 "
                 "{%0,%1,%2,%3}, {%4,%5,%6,%7}, {%8,%9}, {%0,%1,%2,%3};"
                 : "+f"(c0), "+f"(c1), "+f"(c2), "+f"(c3)
                 : "r"(a0), "r"(a1), "r"(a2), "r"(a3), "r"(b0), "r"(b1));
}

// ================= warp-MMA tf32 GEMM =================
// C[M,N] = epi(alpha * A[M,K] @ B[N,K]^T)
// BM=256 BN=128 BK=32, 256 threads (8 warps, 4x2 of 64x64 warp tiles), 3-stage cp.async.
#define GBM 256
#define GBN 128
#define GBK 32
#define GSTAGES 3
#define ROWF 36                               // padded row length in floats (144 B)
#define A_STAGE_F (GBM * ROWF)                // 9216 floats
#define B_STAGE_F (GBN * ROWF)                // 4608 floats
#define STAGE_F   (A_STAGE_F + B_STAGE_F)     // 13824 floats
#define GEMM_SMEM (GSTAGES * STAGE_F * 4)     // 165888 bytes

// EPI: 0=none, 1=relu^2 + tf32 round, 2=add residual
template<int EPI>
__global__ void __launch_bounds__(256, 1)
tf32_gemm_kernel(const float* __restrict__ A, const float* __restrict__ B,
                 float* __restrict__ C, const float* __restrict__ addsrc,
                 const float* __restrict__ alpha_ptr, int alpha_idx,
                 int N, int K)
{
    extern __shared__ float smf[];
    const int tid = threadIdx.x;
    const int wid = tid >> 5, lane = tid & 31;
    const int g = lane >> 2, tig = lane & 3;
    const int wm = (wid & 3) * 64, wn = (wid >> 2) * 64;
    const int bn = blockIdx.x, bm = blockIdx.y;
    const int nk = K / GBK;
    const uint32_t sb = smem_u32(smf);

    const float* Agm = A + (size_t)bm * GBM * K;
    const float* Bgm = B + (size_t)bn * GBN * K;

    // ---- tile loader (cp.async) ----
    auto load_tile = [&](int stage, int ktile) {
        uint32_t sa = sb + stage * (STAGE_F * 4);
        uint32_t sB = sa + A_STAGE_F * 4;
        int kt = ktile * GBK;
        #pragma unroll
        for (int i = 0; i < 8; i++) {                 // A: 2048 chunks of 16B
            int c = tid + i * 256;
            int row = c >> 3, co = (c & 7) * 4;
            cp_async16(sa + (uint32_t)row * 144 + (co << 2),
                       Agm + (size_t)row * K + kt + co);
        }
        #pragma unroll
        for (int i = 0; i < 4; i++) {                 // B: 1024 chunks
            int c = tid + i * 256;
            int row = c >> 3, co = (c & 7) * 4;
            cp_async16(sB + (uint32_t)row * 144 + (co << 2),
                       Bgm + (size_t)row * K + kt + co);
        }
    };

    float acc[4][8][4];
    #pragma unroll
    for (int mt = 0; mt < 4; mt++)
        #pragma unroll
        for (int nt = 0; nt < 8; nt++)
            #pragma unroll
            for (int q = 0; q < 4; q++) acc[mt][nt][q] = 0.f;

    // prefetch
    #pragma unroll
    for (int s = 0; s < GSTAGES - 1; s++) { load_tile(s, s); cp_async_commit(); }

    for (int k = 0; k < nk; k++) {
        cp_async_wait<GSTAGES - 2>();
        __syncthreads();
        const float* As = smf + (k % GSTAGES) * STAGE_F;
        const float* Bs = As + A_STAGE_F;
        #pragma unroll
        for (int ks = 0; ks < 4; ks++) {
            const int k0 = ks * 8;
            uint32_t a[4][4];
            #pragma unroll
            for (int mt = 0; mt < 4; mt++) {
                int m = wm + mt * 16 + g;
                a[mt][0] = __float_as_uint(As[(size_t)m * ROWF + k0 + tig]);
                a[mt][1] = __float_as_uint(As[(size_t)(m + 8) * ROWF + k0 + tig]);
                a[mt][2] = __float_as_uint(As[(size_t)m * ROWF + k0 + tig + 4]);
                a[mt][3] = __float_as_uint(As[(size_t)(m + 8) * ROWF + k0 + tig + 4]);
            }
            #pragma unroll
            for (int nt = 0; nt < 8; nt++) {
                int n = wn + nt * 8 + g;
                uint32_t b0 = __float_as_uint(Bs[(size_t)n * ROWF + k0 + tig]);
                uint32_t b1 = __float_as_uint(Bs[(size_t)n * ROWF + k0 + tig + 4]);
                #pragma unroll
                for (int mt = 0; mt < 4; mt++)
                    mma_tf32(acc[mt][nt][0], acc[mt][nt][1], acc[mt][nt][2], acc[mt][nt][3],
                             a[mt][0], a[mt][1], a[mt][2], a[mt][3], b0, b1);
            }
        }
        __syncthreads();
        if (k + GSTAGES - 1 < nk) load_tile((k + GSTAGES - 1) % GSTAGES, k + GSTAGES - 1);
        cp_async_commit();
    }

    // ---- epilogue ----
    float alpha = alpha_ptr ? alpha_ptr[alpha_idx] : 1.0f;
    #pragma unroll
    for (int mt = 0; mt < 4; mt++) {
        #pragma unroll
        for (int half = 0; half < 2; half++) {
            int row = bm * GBM + wm + mt * 16 + g + half * 8;
            #pragma unroll
            for (int nt = 0; nt < 8; nt++) {
                int col = bn * GBN + wn + nt * 8 + tig * 2;
                float2 v;
                v.x = acc[mt][nt][half * 2 + 0] * alpha;
                v.y = acc[mt][nt][half * 2 + 1] * alpha;
                size_t idx = (size_t)row * N + col;
                if (EPI == 1) {
                    v.x = fmaxf(v.x, 0.f); v.x = to_tf32(v.x * v.x);
                    v.y = fmaxf(v.y, 0.f); v.y = to_tf32(v.y * v.y);
                } else if (EPI == 2) {
                    float2 a2 = *(const float2*)&addsrc[idx];
                    v.x += a2.x; v.y += a2.y;
                }
                *(float2*)&C[idx] = v;
            }
        }
    }
}

// ---------------- weight conversion kernels ----------------
__global__ void __launch_bounds__(256) round_tf32_kernel(const float* __restrict__ in,
                                                         float* __restrict__ outp, int n4) {
    int i = blockIdx.x * 256 + threadIdx.x;
    if (i < n4) {
        float4 v = ((const float4*)in)[i];
        v.x = to_tf32(v.x); v.y = to_tf32(v.y); v.z = to_tf32(v.z); v.w = to_tf32(v.w);
        ((float4*)outp)[i] = v;
    }
}
// out[DIM, FFN] = round_tf32(in[FFN, DIM]^T)
__global__ void __launch_bounds__(256) transpose_round_kernel(const float* __restrict__ in,
                                                              float* __restrict__ outp) {
    __shared__ float t[32][33];
    int bx = blockIdx.x;   // over DIM/32
    int by = blockIdx.y;   // over FFN/32
    int x = threadIdx.x, y = threadIdx.y;    // 32 x 8
    #pragma unroll
    for (int i = 0; i < 32; i += 8)
        t[y + i][x] = in[(size_t)(by * 32 + y + i) * DIM + bx * 32 + x];
    __syncthreads();
    #pragma unroll
    for (int i = 0; i < 32; i += 8)
        outp[(size_t)(bx * 32 + y + i) * FFN + by * 32 + x] = to_tf32(t[x][y + i]);
}

// ---------------- RMSNorm (tf32-rounded output) ----------------
__global__ void __launch_bounds__(256) rmsnorm_kernel(const float* __restrict__ in,
                                                      float* __restrict__ outp) {
    int t = blockIdx.x;
    const float* r = in + (size_t)t * DIM;
    float ss = 0.f;
    for (int i = threadIdx.x; i < DIM; i += 256) { float v = r[i]; ss += v * v; }
    __shared__ float sred[8];
    for (int o = 16; o; o >>= 1) ss += __shfl_xor_sync(0xffffffffu, ss, o);
    if ((threadIdx.x & 31) == 0) sred[threadIdx.x >> 5] = ss;
    __syncthreads();
    float tot = 0.f;
    #pragma unroll
    for (int i = 0; i < 8; i++) tot += sred[i];
    float scale = rsqrtf(tot / (float)DIM + EPS_F);
    for (int i = threadIdx.x; i < DIM; i += 256)
        outp[(size_t)t * DIM + i] = to_tf32(r[i] * scale);
}

// ---------------- per-(t, head-slot) QK rmsnorm + rotary ----------------
__global__ void __launch_bounds__(128) qkrot_kernel(
    float* __restrict__ qkv, float* __restrict__ krot,
    const float* __restrict__ cosb, const float* __restrict__ sinb)
{
    int hs = blockIdx.x;
    int t  = blockIdx.y;
    int d  = threadIdx.x;
    float v = qkv[((size_t)t * 48 + hs) * HD + d];
    __shared__ float sm[HD];
    __shared__ float red[4];
    float ss = v * v;
    for (int o = 16; o; o >>= 1) ss += __shfl_xor_sync(0xffffffffu, ss, o);
    if ((d & 31) == 0) red[d >> 5] = ss;
    __syncthreads();
    float tot = red[0] + red[1] + red[2] + red[3];
    float n = v * rsqrtf(tot / (float)HD + EPS_F);
    sm[d] = n;
    __syncthreads();
    float o;
    if (d < 64) {
        float c = cosb[t * 64 + d], s = sinb[t * 64 + d];
        o = sm[d] * c + sm[d + 64] * s;
    } else {
        float c = cosb[t * 64 + d - 64], s = sinb[t * 64 + d - 64];
        o = -sm[d - 64] * s + sm[d] * c;
    }
    if (hs < 16) qkv[((size_t)t * 48 + hs) * HD + d] = o;
    else         krot[((size_t)t * NH + (hs - 16)) * HD + d] = o;
}

// ---------------- key-offset shift ----------------
__global__ void __launch_bounds__(256) kshift_kernel(
    const float* __restrict__ krot, float* __restrict__ qkv,
    const int* __restrict__ key_offset)
{
    int idx = blockIdx.x * 256 + threadIdx.x;
    int d = idx & 127;
    int h = (idx >> 7) & 15;
    int t = idx >> 11;
    int ko = key_offset[0];
    bool up = (d >= 32 && d < 64) || (d >= 96);
    int st = (ko && up && t > 0) ? (t - 1) : t;
    qkv[((size_t)t * 48 + 16 + h) * HD + d] = krot[((size_t)st * NH + h) * HD + d];
}

// ---------------- gate logits ----------------
__global__ void __launch_bounds__(256) gates_kernel(
    const float* __restrict__ xn, const float* __restrict__ agw,
    const float* __restrict__ vgw, float* __restrict__ agate,
    float* __restrict__ vgate)
{
    int t = blockIdx.x;
    int w = threadIdx.x >> 5, lane = threadIdx.x & 31;
    const float* xr = xn + (size_t)t * DIM;
    float acc[4] = {};
    const float* wbase[4];
    #pragma unroll
    for (int q = 0; q < 4; q++) {
        int o = w * 4 + q;
        wbase[q] = (o < 16) ? (agw + (size_t)o * DIM) : (vgw + (size_t)(o - 16) * DIM);
    }
    for (int dd = lane; dd < DIM; dd += 32) {
        float xv = xr[dd];
        #pragma unroll
        for (int q = 0; q < 4; q++) acc[q] = fmaf(xv, wbase[q][dd], acc[q]);
    }
    #pragma unroll
    for (int q = 0; q < 4; q++)
        for (int o2 = 16; o2; o2 >>= 1) acc[q] += __shfl_xor_sync(0xffffffffu, acc[q], o2);
    if (lane == 0) {
        #pragma unroll
        for (int q = 0; q < 4; q++) {
            int o = w * 4 + q;
            float g = 1.f / (1.f + expf(-acc[q]));
            if (o < 16) agate[t * NH + o] = g;
            else        vgate[t * NH + (o - 16)] = g;
        }
    }
}

// ---------------- v += ve_gate * ve ----------------
__global__ void __launch_bounds__(256) vupdate_kernel(
    float* __restrict__ qkv, const float* __restrict__ ve,
    const float* __restrict__ vgate)
{
    int idx = blockIdx.x * 256 + threadIdx.x;
    int d = idx & 127;
    int h = (idx >> 7) & 15;
    int t = idx >> 11;
    float g = vgate[t * NH + h];
    qkv[((size_t)t * 48 + 32 + h) * HD + d] += g * ve[idx];
}

// ---------------- flash attention (fp32) ----------------
#define F_QT 0
#define F_KT 8192
#define F_VS 16384
#define F_PT 24576
#define F_RED 28672
#define F_M  29696
#define F_L  29760
#define F_AL 29824
#define F_KD 29888
#define F_QD 29952
#define F_TOTAL 30016
#define FLASH_SMEM_BYTES (F_TOTAL * 4)

__global__ void __launch_bounds__(256) flash_kernel(
    const float* __restrict__ qkv, const int* __restrict__ docs,
    const float* __restrict__ attn_scale, const float* __restrict__ agate,
    float* __restrict__ y)
{
    extern __shared__ float fsm[];
    float* Qt   = fsm + F_QT;
    float* Kt   = fsm + F_KT;
    float* Vs   = fsm + F_VS;
    float* Pt   = fsm + F_PT;
    float* red  = fsm + F_RED;
    float* mrow = fsm + F_M;
    float* lrow = fsm + F_L;
    float* arow = fsm + F_AL;
    int*   kd   = (int*)(fsm + F_KD);
    int*   qd   = (int*)(fsm + F_QD);

    int tid = threadIdx.x;
    int h  = blockIdx.y;
    int qi = blockIdx.x;
    int qbase = qi * 64;
    int ty = tid >> 4, tx = tid & 15;
    int row0 = ty * 4;
    float scale = attn_scale[0];

    #pragma unroll
    for (int l = 0; l < 8; l++) {
        int id = tid + l * 256;
        int r = id >> 5;
        int c = (id & 31) * 4;
        float4 f = *(const float4*)&qkv[((size_t)(qbase + r) * 48 + h) * HD + c];
        Qt[(c + 0) * 64 + r] = f.x; Qt[(c + 1) * 64 + r] = f.y;
        Qt[(c + 2) * 64 + r] = f.z; Qt[(c + 3) * 64 + r] = f.w;
    }
    if (tid < 64) {
        qd[tid]   = docs[qbase + tid];
        mrow[tid] = NEG_INF_F;
        lrow[tid] = 0.f;
    }
    float o[4][8] = {};
    __syncthreads();

    for (int kb = 0; kb <= qi; kb++) {
        int kbase = kb * 64;
        #pragma unroll
        for (int l = 0; l < 8; l++) {
            int id = tid + l * 256;
            int r = id >> 5;
            int c = (id & 31) * 4;
            float4 f = *(const float4*)&qkv[((size_t)(kbase + r) * 48 + 16 + h) * HD + c];
            Kt[(c + 0) * 64 + r] = f.x; Kt[(c + 1) * 64 + r] = f.y;
            Kt[(c + 2) * 64 + r] = f.z; Kt[(c + 3) * 64 + r] = f.w;
            float4 g = *(const float4*)&qkv[((size_t)(kbase + r) * 48 + 32 + h) * HD + c];
            *(float4*)&Vs[r * 128 + c] = g;
        }
        if (tid < 64) kd[tid] = docs[kbase + tid];
        __syncthreads();

        float s[4][4] = {};
        for (int d = 0; d < HD; d++) {
            float a[4], b[4];
            #pragma unroll
            for (int i = 0; i < 4; i++) a[i] = Qt[d * 64 + row0 + i];
            #pragma unroll
            for (int j = 0; j < 4; j++) b[j] = Kt[d * 64 + tx * 4 + j];
            #pragma unroll
            for (int i = 0; i < 4; i++)
                #pragma unroll
                for (int j = 0; j < 4; j++)
                    s[i][j] = fmaf(a[i], b[j], s[i][j]);
        }
        #pragma unroll
        for (int i = 0; i < 4; i++) {
            int tg = qbase + row0 + i;
            int dq = qd[row0 + i];
            float mx = NEG_INF_F;
            #pragma unroll
            for (int j = 0; j < 4; j++) {
                int sg = kbase + tx * 4 + j;
                float v = s[i][j] * scale;
                bool valid = (sg <= tg) && (kd[tx * 4 + j] == dq);
                v = valid ? v : NEG_INF_F;
                s[i][j] = v;
                mx = fmaxf(mx, v);
            }
            red[(row0 + i) * 16 + tx] = mx;
        }
        __syncthreads();
        if (tid < 64) {
            float mx = red[tid * 16];
            #pragma unroll
            for (int j = 1; j < 16; j++) mx = fmaxf(mx, red[tid * 16 + j]);
            float mo = mrow[tid];
            float mn = fmaxf(mo, mx);
            mrow[tid] = mn;
            arow[tid] = expf(mo - mn);
        }
        __syncthreads();
        #pragma unroll
        for (int i = 0; i < 4; i++) {
            float al = arow[row0 + i];
            #pragma unroll
            for (int j = 0; j < 8; j++) o[i][j] *= al;
        }
        #pragma unroll
        for (int i = 0; i < 4; i++) {
            float mn = mrow[row0 + i];
            float sum = 0.f;
            #pragma unroll
            for (int j = 0; j < 4; j++) {
                float v = s[i][j];
                float p = (v > -1e29f) ? expf(v - mn) : 0.f;
                Pt[(tx * 4 + j) * 64 + row0 + i] = p;
                sum += p;
            }
            red[(row0 + i) * 16 + tx] = sum;
        }
        __syncthreads();
        if (tid < 64) {
            float sm = 0.f;
            #pragma unroll
            for (int j = 0; j < 16; j++) sm += red[tid * 16 + j];
            lrow[tid] = lrow[tid] * arow[tid] + sm;
        }
        #pragma unroll 8
        for (int kk = 0; kk < 64; kk++) {
            float p[4];
            #pragma unroll
            for (int i = 0; i < 4; i++) p[i] = Pt[kk * 64 + row0 + i];
            float4 v0 = *(float4*)&Vs[kk * 128 + tx * 8];
            float4 v1 = *(float4*)&Vs[kk * 128 + tx * 8 + 4];
            float vb[8] = {v0.x, v0.y, v0.z, v0.w, v1.x, v1.y, v1.z, v1.w};
            #pragma unroll
            for (int i = 0; i < 4; i++)
                #pragma unroll
                for (int j = 0; j < 8; j++)
                    o[i][j] = fmaf(p[i], vb[j], o[i][j]);
        }
        __syncthreads();
    }

    #pragma unroll
    for (int i = 0; i < 4; i++) {
        int t = qbase + row0 + i;
        float f = (1.0f / lrow[row0 + i]) * agate[t * NH + h];
        #pragma unroll
        for (int j = 0; j < 8; j++)
            y[(size_t)t * DIM + h * HD + tx * 8 + j] = to_tf32(o[i][j] * f);
    }
}

// ---------------- launch ----------------
extern "C" void kernel_launch(void* const* d_in, const int* in_sizes, int n_in,
                              void* d_out, int out_size) {
    const float* x           = (const float*)d_in[0];
    const float* ve          = (const float*)d_in[1];
    const float* qkvo_w      = (const float*)d_in[2];
    const float* attn_gate_w = (const float*)d_in[3];
    const float* ve_gate_w   = (const float*)d_in[4];
    const float* c_fc        = (const float*)d_in[5];
    const float* c_proj      = (const float*)d_in[6];
    const float* sa_lambdas  = (const float*)d_in[7];
    const float* cosb        = (const float*)d_in[8];
    const float* sinb        = (const float*)d_in[9];
    const float* attn_scale  = (const float*)d_in[10];
    const int*   docs        = (const int*)d_in[11];
    const int*   key_offset  = (const int*)d_in[12];
    float*       out         = (float*)d_out;

    float *xn, *qkv, *krot, *y, *x1, *hbuf, *agate, *vgate, *wqkv, *wfc, *wpT;
    cudaGetSymbolAddress((void**)&xn,    g_xn);
    cudaGetSymbolAddress((void**)&qkv,   g_qkv);
    cudaGetSymbolAddress((void**)&krot,  g_krot);
    cudaGetSymbolAddress((void**)&y,     g_y);
    cudaGetSymbolAddress((void**)&x1,    g_x1);
    cudaGetSymbolAddress((void**)&hbuf,  g_h);
    cudaGetSymbolAddress((void**)&agate, g_agate);
    cudaGetSymbolAddress((void**)&vgate, g_vgate);
    cudaGetSymbolAddress((void**)&wqkv,  g_wqkv);
    cudaGetSymbolAddress((void**)&wfc,   g_wfc);
    cudaGetSymbolAddress((void**)&wpT,   g_wpT);

    cudaFuncSetAttribute(flash_kernel, cudaFuncAttributeMaxDynamicSharedMemorySize,
                         FLASH_SMEM_BYTES);
    cudaFuncSetAttribute(tf32_gemm_kernel<0>, cudaFuncAttributeMaxDynamicSharedMemorySize,
                         GEMM_SMEM);
    cudaFuncSetAttribute(tf32_gemm_kernel<1>, cudaFuncAttributeMaxDynamicSharedMemorySize,
                         GEMM_SMEM);
    cudaFuncSetAttribute(tf32_gemm_kernel<2>, cudaFuncAttributeMaxDynamicSharedMemorySize,
                         GEMM_SMEM);

    // weight conversions (rounded tf32 copies; c_proj also transposed to [N,K])
    round_tf32_kernel<<<(4 * DIM * DIM / 4 + 255) / 256, 256>>>(qkvo_w, wqkv, 4 * DIM * DIM / 4);
    round_tf32_kernel<<<((size_t)FFN * DIM / 4 + 255) / 256, 256>>>(c_fc, wfc, FFN * DIM / 4);
    transpose_round_kernel<<<dim3(DIM / 32, FFN / 32), dim3(32, 8)>>>(c_proj, wpT);

    // 1. xn = round_tf32(rmsnorm(x))
    rmsnorm_kernel<<<T_SEQ, 256>>>(x, xn);
    // 2. qkv = lam0 * xn @ Wqkv^T   (M=2048, N=6144, K=2048)
    tf32_gemm_kernel<0><<<dim3(3 * DIM / GBN, T_SEQ / GBM), 256, GEMM_SMEM>>>(
        xn, wqkv, qkv, nullptr, sa_lambdas, 0, 3 * DIM, DIM);
    // 3. per-head rmsnorm + rotary
    qkrot_kernel<<<dim3(32, T_SEQ), 128>>>(qkv, krot, cosb, sinb);
    // 4. key-offset shift
    kshift_kernel<<<(T_SEQ * NH * HD) / 256, 256>>>(krot, qkv, key_offset);
    // 5. gates
    gates_kernel<<<T_SEQ, 256>>>(xn, attn_gate_w, ve_gate_w, agate, vgate);
    // 6. v update
    vupdate_kernel<<<(T_SEQ * DIM) / 256, 256>>>(qkv, ve, vgate);
    // 7. flash attention
    flash_kernel<<<dim3(T_SEQ / 64, NH), 256, FLASH_SMEM_BYTES>>>(
        qkv, docs, attn_scale, agate, y);
    // 8. x1 = x + lam1 * y @ Wo^T
    tf32_gemm_kernel<2><<<dim3(DIM / GBN, T_SEQ / GBM), 256, GEMM_SMEM>>>(
        y, wqkv + (size_t)3 * DIM * DIM, x1, x, sa_lambdas, 1, DIM, DIM);
    // 9. xn = round_tf32(rmsnorm(x1))
    rmsnorm_kernel<<<T_SEQ, 256>>>(x1, xn);
    // 10. h = round_tf32(relu(xn @ c_fc^T)^2)
    tf32_gemm_kernel<1><<<dim3(FFN / GBN, T_SEQ / GBM), 256, GEMM_SMEM>>>(
        xn, wfc, hbuf, nullptr, nullptr, 0, FFN, DIM);
    // 11. out = x1 + h @ c_proj   (via c_proj^T, K=8192)
    tf32_gemm_kernel<2><<<dim3(DIM / GBN, T_SEQ / GBM), 256, GEMM_SMEM>>>(
        hbuf, wpT, out, x1, nullptr, 0, DIM, FFN);
}

// round 4
// speedup vs baseline: 3.9415x; 1.6964x over previous
#include <cuda_runtime.h>
#include <cuda_bf16.h>
#include <cstdint>
#include <cstddef>

// ---------------- problem constants ----------------
#define T_SEQ 2048
#define DIM   2048
#define NH    16
#define HD    128
#define FFN   8192
#define EPS_F 1.1920929e-07f
#define NEG_INF_F (-1e30f)

// ---------------- scratch (device globals; no runtime allocs) ----------------
__device__ float g_xn  [(size_t)T_SEQ * DIM];
__device__ float g_qkv [(size_t)T_SEQ * 3 * DIM];
__device__ float g_krot[(size_t)T_SEQ * NH * HD];
__device__ float g_y   [(size_t)T_SEQ * DIM];
__device__ float g_x1  [(size_t)T_SEQ * DIM];
__device__ float g_h   [(size_t)T_SEQ * FFN];
__device__ float g_agate[(size_t)T_SEQ * NH];
__device__ float g_vgate[(size_t)T_SEQ * NH];
__device__ float g_wqkv[(size_t)4 * DIM * DIM];   // tf32-rounded qkvo weights
__device__ float g_wfc [(size_t)FFN * DIM];       // tf32-rounded c_fc
__device__ float g_wpT [(size_t)DIM * FFN];       // tf32-rounded c_proj^T [DIM, FFN]

// ---------------- helpers ----------------
__device__ __forceinline__ float to_tf32(float x) {
    asm("cvt.rna.tf32.f32 %0, %1;" : "=f"(x) : "f"(x));
    return x;
}
__device__ __forceinline__ void cp_async16(uint32_t dst, const float* src) {
    asm volatile("cp.async.cg.shared.global [%0], [%1], 16;" :: "r"(dst), "l"(src));
}
__device__ __forceinline__ void cp_async_commit() {
    asm volatile("cp.async.commit_group;" ::: "memory");
}
template<int N>
__device__ __forceinline__ void cp_async_wait() {
    asm volatile("cp.async.wait_group %0;" :: "n"(N) : "memory");
}
__device__ __forceinline__ uint32_t smem_u32(const void* p) {
    uint32_t a;
    asm("{ .reg .u64 t; cvta.to.shared.u64 t, %1; cvt.u32.u64 %0, t; }" : "=r"(a) : "l"(p));
    return a;
}
__device__ __forceinline__ void mma_tf32(float& c0, float& c1, float& c2, float& c3,
                                         uint32_t a0, uint32_t a1, uint32_t a2, uint32_t a3,
                                         uint32_t b0, uint32_t b1) {
    asm volatile("mma.sync.aligned.m16n8k8.row.col.f32.tf32.tf32.f32 "
                 "{%0,%1,%2,%3}, {%4,%5,%6,%7}, {%8,%9}, {%0,%1,%2,%3};"
                 : "+f"(c0), "+f"(c1), "+f"(c2), "+f"(c3)
                 : "r"(a0), "r"(a1), "r"(a2), "r"(a3), "r"(b0), "r"(b1));
}

// ================= warp-MMA tf32 GEMM =================
// C[M,N] = epi(alpha * A[M,K] @ B[N,K]^T)
// BM=256 BN=128 BK=32, 256 threads (8 warps, 4x2 of 64x64 warp tiles), 3-stage cp.async.
#define GBM 256
#define GBN 128
#define GBK 32
#define GSTAGES 3
#define ROWF 36                               // padded row length in floats (144 B)
#define A_STAGE_F (GBM * ROWF)                // 9216 floats
#define B_STAGE_F (GBN * ROWF)                // 4608 floats
#define STAGE_F   (A_STAGE_F + B_STAGE_F)     // 13824 floats
#define GEMM_SMEM (GSTAGES * STAGE_F * 4)     // 165888 bytes

// EPI: 0=none, 1=relu^2 + tf32 round, 2=add residual
template<int EPI>
__global__ void __launch_bounds__(256, 1)
tf32_gemm_kernel(const float* __restrict__ A, const float* __restrict__ B,
                 float* __restrict__ C, const float* __restrict__ addsrc,
                 const float* __restrict__ alpha_ptr, int alpha_idx,
                 int N, int K)
{
    extern __shared__ float smf[];
    const int tid = threadIdx.x;
    const int wid = tid >> 5, lane = tid & 31;
    const int g = lane >> 2, tig = lane & 3;
    const int wm = (wid & 3) * 64, wn = (wid >> 2) * 64;
    const int bn = blockIdx.x, bm = blockIdx.y;
    const int nk = K / GBK;
    const uint32_t sb = smem_u32(smf);

    const float* Agm = A + (size_t)bm * GBM * K;
    const float* Bgm = B + (size_t)bn * GBN * K;

    auto load_tile = [&](int stage, int ktile) {
        uint32_t sa = sb + stage * (STAGE_F * 4);
        uint32_t sB = sa + A_STAGE_F * 4;
        int kt = ktile * GBK;
        #pragma unroll
        for (int i = 0; i < 8; i++) {                 // A: 2048 chunks of 16B
            int c = tid + i * 256;
            int row = c >> 3, co = (c & 7) * 4;
            cp_async16(sa + (uint32_t)row * 144 + (co << 2),
                       Agm + (size_t)row * K + kt + co);
        }
        #pragma unroll
        for (int i = 0; i < 4; i++) {                 // B: 1024 chunks
            int c = tid + i * 256;
            int row = c >> 3, co = (c & 7) * 4;
            cp_async16(sB + (uint32_t)row * 144 + (co << 2),
                       Bgm + (size_t)row * K + kt + co);
        }
    };

    float acc[4][8][4];
    #pragma unroll
    for (int mt = 0; mt < 4; mt++)
        #pragma unroll
        for (int nt = 0; nt < 8; nt++)
            #pragma unroll
            for (int q = 0; q < 4; q++) acc[mt][nt][q] = 0.f;

    #pragma unroll
    for (int s = 0; s < GSTAGES - 1; s++) { load_tile(s, s); cp_async_commit(); }

    for (int k = 0; k < nk; k++) {
        cp_async_wait<GSTAGES - 2>();
        __syncthreads();
        const float* As = smf + (k % GSTAGES) * STAGE_F;
        const float* Bs = As + A_STAGE_F;
        #pragma unroll
        for (int ks = 0; ks < 4; ks++) {
            const int k0 = ks * 8;
            uint32_t a[4][4];
            #pragma unroll
            for (int mt = 0; mt < 4; mt++) {
                int m = wm + mt * 16 + g;
                a[mt][0] = __float_as_uint(As[(size_t)m * ROWF + k0 + tig]);
                a[mt][1] = __float_as_uint(As[(size_t)(m + 8) * ROWF + k0 + tig]);
                a[mt][2] = __float_as_uint(As[(size_t)m * ROWF + k0 + tig + 4]);
                a[mt][3] = __float_as_uint(As[(size_t)(m + 8) * ROWF + k0 + tig + 4]);
            }
            #pragma unroll
            for (int nt = 0; nt < 8; nt++) {
                int n = wn + nt * 8 + g;
                uint32_t b0 = __float_as_uint(Bs[(size_t)n * ROWF + k0 + tig]);
                uint32_t b1 = __float_as_uint(Bs[(size_t)n * ROWF + k0 + tig + 4]);
                #pragma unroll
                for (int mt = 0; mt < 4; mt++)
                    mma_tf32(acc[mt][nt][0], acc[mt][nt][1], acc[mt][nt][2], acc[mt][nt][3],
                             a[mt][0], a[mt][1], a[mt][2], a[mt][3], b0, b1);
            }
        }
        __syncthreads();
        if (k + GSTAGES - 1 < nk) load_tile((k + GSTAGES - 1) % GSTAGES, k + GSTAGES - 1);
        cp_async_commit();
    }

    float alpha = alpha_ptr ? alpha_ptr[alpha_idx] : 1.0f;
    #pragma unroll
    for (int mt = 0; mt < 4; mt++) {
        #pragma unroll
        for (int half = 0; half < 2; half++) {
            int row = bm * GBM + wm + mt * 16 + g + half * 8;
            #pragma unroll
            for (int nt = 0; nt < 8; nt++) {
                int col = bn * GBN + wn + nt * 8 + tig * 2;
                float2 v;
                v.x = acc[mt][nt][half * 2 + 0] * alpha;
                v.y = acc[mt][nt][half * 2 + 1] * alpha;
                size_t idx = (size_t)row * N + col;
                if (EPI == 1) {
                    v.x = fmaxf(v.x, 0.f); v.x = to_tf32(v.x * v.x);
                    v.y = fmaxf(v.y, 0.f); v.y = to_tf32(v.y * v.y);
                } else if (EPI == 2) {
                    float2 a2 = *(const float2*)&addsrc[idx];
                    v.x += a2.x; v.y += a2.y;
                }
                *(float2*)&C[idx] = v;
            }
        }
    }
}

// ---------------- weight conversion kernels ----------------
__global__ void __launch_bounds__(256) round_tf32_kernel(const float* __restrict__ in,
                                                         float* __restrict__ outp, int n4) {
    int i = blockIdx.x * 256 + threadIdx.x;
    if (i < n4) {
        float4 v = ((const float4*)in)[i];
        v.x = to_tf32(v.x); v.y = to_tf32(v.y); v.z = to_tf32(v.z); v.w = to_tf32(v.w);
        ((float4*)outp)[i] = v;
    }
}
__global__ void __launch_bounds__(256) transpose_round_kernel(const float* __restrict__ in,
                                                              float* __restrict__ outp) {
    __shared__ float t[32][33];
    int bx = blockIdx.x;   // over DIM/32
    int by = blockIdx.y;   // over FFN/32
    int x = threadIdx.x, y = threadIdx.y;    // 32 x 8
    #pragma unroll
    for (int i = 0; i < 32; i += 8)
        t[y + i][x] = in[(size_t)(by * 32 + y + i) * DIM + bx * 32 + x];
    __syncthreads();
    #pragma unroll
    for (int i = 0; i < 32; i += 8)
        outp[(size_t)(bx * 32 + y + i) * FFN + by * 32 + x] = to_tf32(t[x][y + i]);
}

// ---------------- RMSNorm (tf32-rounded output) ----------------
__global__ void __launch_bounds__(256) rmsnorm_kernel(const float* __restrict__ in,
                                                      float* __restrict__ outp) {
    int t = blockIdx.x;
    const float* r = in + (size_t)t * DIM;
    float ss = 0.f;
    for (int i = threadIdx.x; i < DIM; i += 256) { float v = r[i]; ss += v * v; }
    __shared__ float sred[8];
    for (int o = 16; o; o >>= 1) ss += __shfl_xor_sync(0xffffffffu, ss, o);
    if ((threadIdx.x & 31) == 0) sred[threadIdx.x >> 5] = ss;
    __syncthreads();
    float tot = 0.f;
    #pragma unroll
    for (int i = 0; i < 8; i++) tot += sred[i];
    float scale = rsqrtf(tot / (float)DIM + EPS_F);
    for (int i = threadIdx.x; i < DIM; i += 256)
        outp[(size_t)t * DIM + i] = to_tf32(r[i] * scale);
}

// ---------------- per-(t, head-slot) QK rmsnorm + rotary (tf32-rounded out) ----------------
__global__ void __launch_bounds__(128) qkrot_kernel(
    float* __restrict__ qkv, float* __restrict__ krot,
    const float* __restrict__ cosb, const float* __restrict__ sinb)
{
    int hs = blockIdx.x;
    int t  = blockIdx.y;
    int d  = threadIdx.x;
    float v = qkv[((size_t)t * 48 + hs) * HD + d];
    __shared__ float sm[HD];
    __shared__ float red[4];
    float ss = v * v;
    for (int o = 16; o; o >>= 1) ss += __shfl_xor_sync(0xffffffffu, ss, o);
    if ((d & 31) == 0) red[d >> 5] = ss;
    __syncthreads();
    float tot = red[0] + red[1] + red[2] + red[3];
    float n = v * rsqrtf(tot / (float)HD + EPS_F);
    sm[d] = n;
    __syncthreads();
    float o;
    if (d < 64) {
        float c = cosb[t * 64 + d], s = sinb[t * 64 + d];
        o = sm[d] * c + sm[d + 64] * s;
    } else {
        float c = cosb[t * 64 + d - 64], s = sinb[t * 64 + d - 64];
        o = -sm[d - 64] * s + sm[d] * c;
    }
    o = to_tf32(o);
    if (hs < 16) qkv[((size_t)t * 48 + hs) * HD + d] = o;
    else         krot[((size_t)t * NH + (hs - 16)) * HD + d] = o;
}

// ---------------- key-offset shift ----------------
__global__ void __launch_bounds__(256) kshift_kernel(
    const float* __restrict__ krot, float* __restrict__ qkv,
    const int* __restrict__ key_offset)
{
    int idx = blockIdx.x * 256 + threadIdx.x;
    int d = idx & 127;
    int h = (idx >> 7) & 15;
    int t = idx >> 11;
    int ko = key_offset[0];
    bool up = (d >= 32 && d < 64) || (d >= 96);
    int st = (ko && up && t > 0) ? (t - 1) : t;
    qkv[((size_t)t * 48 + 16 + h) * HD + d] = krot[((size_t)st * NH + h) * HD + d];
}

// ---------------- gate logits ----------------
__global__ void __launch_bounds__(256) gates_kernel(
    const float* __restrict__ xn, const float* __restrict__ agw,
    const float* __restrict__ vgw, float* __restrict__ agate,
    float* __restrict__ vgate)
{
    int t = blockIdx.x;
    int w = threadIdx.x >> 5, lane = threadIdx.x & 31;
    const float* xr = xn + (size_t)t * DIM;
    float acc[4] = {};
    const float* wbase[4];
    #pragma unroll
    for (int q = 0; q < 4; q++) {
        int o = w * 4 + q;
        wbase[q] = (o < 16) ? (agw + (size_t)o * DIM) : (vgw + (size_t)(o - 16) * DIM);
    }
    for (int dd = lane; dd < DIM; dd += 32) {
        float xv = xr[dd];
        #pragma unroll
        for (int q = 0; q < 4; q++) acc[q] = fmaf(xv, wbase[q][dd], acc[q]);
    }
    #pragma unroll
    for (int q = 0; q < 4; q++)
        for (int o2 = 16; o2; o2 >>= 1) acc[q] += __shfl_xor_sync(0xffffffffu, acc[q], o2);
    if (lane == 0) {
        #pragma unroll
        for (int q = 0; q < 4; q++) {
            int o = w * 4 + q;
            float g = 1.f / (1.f + expf(-acc[q]));
            if (o < 16) agate[t * NH + o] = g;
            else        vgate[t * NH + (o - 16)] = g;
        }
    }
}

// ---------------- v = round_tf32(v + ve_gate * ve) ----------------
__global__ void __launch_bounds__(256) vupdate_kernel(
    float* __restrict__ qkv, const float* __restrict__ ve,
    const float* __restrict__ vgate)
{
    int idx = blockIdx.x * 256 + threadIdx.x;
    int d = idx & 127;
    int h = (idx >> 7) & 15;
    int t = idx >> 11;
    float g = vgate[t * NH + h];
    size_t o = ((size_t)t * 48 + 32 + h) * HD + d;
    qkv[o] = to_tf32(qkv[o] + g * ve[idx]);
}

// ================= MMA flash attention (tf32) =================
// 64 q-rows x 64 k-cols per tile, 4 warps (each warp: 16 q-rows).
// Doc-block tile skip: docs sorted, so skip tile if docs[kbase+63] < docs[qbase].
#define ROWP 132
#define FL_SMEM ((3 * 64 * ROWP + 64) * 4)

__global__ void __launch_bounds__(128) flash_mma_kernel(
    const float* __restrict__ qkv, const int* __restrict__ docs,
    const float* __restrict__ attn_scale, const float* __restrict__ agate,
    float* __restrict__ y)
{
    extern __shared__ float fs[];
    float* Qs = fs;
    float* Ks = fs + 64 * ROWP;
    float* Vs = fs + 2 * 64 * ROWP;
    int*   kd = (int*)(fs + 3 * 64 * ROWP);

    const int tid = threadIdx.x, wid = tid >> 5, lane = tid & 31;
    const int g = lane >> 2, tig = lane & 3;
    const int h = blockIdx.y;
    const int qi = (int)gridDim.x - 1 - (int)blockIdx.x;   // heavy tiles launch first
    const int qbase = qi * 64;
    const float scale = attn_scale[0];

    // load Q tile (64 x 128)
    #pragma unroll
    for (int i = 0; i < 16; i++) {
        int c = tid + i * 128;
        int r = c >> 5, co = (c & 31) * 4;
        float4 f = *(const float4*)&qkv[((size_t)(qbase + r) * 48 + h) * HD + co];
        *(float4*)&Qs[r * ROWP + co] = f;
    }
    const int rg0 = qbase + wid * 16 + g;
    const int rg1 = rg0 + 8;
    const int qd0 = docs[rg0], qd1 = docs[rg1];
    const int qdmin = docs[qbase];

    float o[16][4] = {};
    float m0 = NEG_INF_F, m1 = NEG_INF_F, l0 = 0.f, l1 = 0.f;
    __syncthreads();

    for (int kb = 0; kb <= qi; kb++) {
        const int kbase = kb * 64;
        if (docs[kbase + 63] < qdmin) continue;     // doc-block skip (uniform)
        __syncthreads();
        #pragma unroll
        for (int i = 0; i < 16; i++) {
            int c = tid + i * 128;
            int r = c >> 5, co = (c & 31) * 4;
            float4 f = *(const float4*)&qkv[((size_t)(kbase + r) * 48 + 16 + h) * HD + co];
            *(float4*)&Ks[r * ROWP + co] = f;
            float4 v4 = *(const float4*)&qkv[((size_t)(kbase + r) * 48 + 32 + h) * HD + co];
            *(float4*)&Vs[r * ROWP + co] = v4;
        }
        if (tid < 64) kd[tid] = docs[kbase + tid];
        __syncthreads();

        // S = Q @ K^T  (per warp: 16 x 64)
        float s[8][4] = {};
        #pragma unroll
        for (int ks = 0; ks < 16; ks++) {
            const int k0 = ks * 8;
            uint32_t a0 = __float_as_uint(Qs[(wid * 16 + g) * ROWP + k0 + tig]);
            uint32_t a1 = __float_as_uint(Qs[(wid * 16 + g + 8) * ROWP + k0 + tig]);
            uint32_t a2 = __float_as_uint(Qs[(wid * 16 + g) * ROWP + k0 + tig + 4]);
            uint32_t a3 = __float_as_uint(Qs[(wid * 16 + g + 8) * ROWP + k0 + tig + 4]);
            #pragma unroll
            for (int nt = 0; nt < 8; nt++) {
                uint32_t b0 = __float_as_uint(Ks[(nt * 8 + g) * ROWP + k0 + tig]);
                uint32_t b1 = __float_as_uint(Ks[(nt * 8 + g) * ROWP + k0 + tig + 4]);
                mma_tf32(s[nt][0], s[nt][1], s[nt][2], s[nt][3], a0, a1, a2, a3, b0, b1);
            }
        }

        // scale + mask + row max
        float mx0 = m0, mx1 = m1;
        #pragma unroll
        for (int nt = 0; nt < 8; nt++) {
            int c0i = kbase + nt * 8 + 2 * tig;
            int d0 = kd[nt * 8 + 2 * tig], d1 = kd[nt * 8 + 2 * tig + 1];
            float v00 = (c0i     <= rg0 && d0 == qd0) ? s[nt][0] * scale : NEG_INF_F;
            float v01 = (c0i + 1 <= rg0 && d1 == qd0) ? s[nt][1] * scale : NEG_INF_F;
            float v10 = (c0i     <= rg1 && d0 == qd1) ? s[nt][2] * scale : NEG_INF_F;
            float v11 = (c0i + 1 <= rg1 && d1 == qd1) ? s[nt][3] * scale : NEG_INF_F;
            s[nt][0] = v00; s[nt][1] = v01; s[nt][2] = v10; s[nt][3] = v11;
            mx0 = fmaxf(mx0, fmaxf(v00, v01));
            mx1 = fmaxf(mx1, fmaxf(v10, v11));
        }
        mx0 = fmaxf(mx0, __shfl_xor_sync(0xffffffffu, mx0, 1));
        mx0 = fmaxf(mx0, __shfl_xor_sync(0xffffffffu, mx0, 2));
        mx1 = fmaxf(mx1, __shfl_xor_sync(0xffffffffu, mx1, 1));
        mx1 = fmaxf(mx1, __shfl_xor_sync(0xffffffffu, mx1, 2));
        float al0 = __expf(m0 - mx0), al1 = __expf(m1 - mx1);
        m0 = mx0; m1 = mx1;

        // P = exp(S - m), row sums
        float sum0 = 0.f, sum1 = 0.f;
        #pragma unroll
        for (int nt = 0; nt < 8; nt++) {
            float p00 = __expf(s[nt][0] - m0);
            float p01 = __expf(s[nt][1] - m0);
            float p10 = __expf(s[nt][2] - m1);
            float p11 = __expf(s[nt][3] - m1);
            sum0 += p00 + p01; sum1 += p10 + p11;
            s[nt][0] = to_tf32(p00); s[nt][1] = to_tf32(p01);
            s[nt][2] = to_tf32(p10); s[nt][3] = to_tf32(p11);
        }
        sum0 += __shfl_xor_sync(0xffffffffu, sum0, 1);
        sum0 += __shfl_xor_sync(0xffffffffu, sum0, 2);
        sum1 += __shfl_xor_sync(0xffffffffu, sum1, 1);
        sum1 += __shfl_xor_sync(0xffffffffu, sum1, 2);
        l0 = l0 * al0 + sum0;
        l1 = l1 * al1 + sum1;
        #pragma unroll
        for (int nt = 0; nt < 16; nt++) {
            o[nt][0] *= al0; o[nt][1] *= al0;
            o[nt][2] *= al1; o[nt][3] *= al1;
        }

        // O += P @ V  (A-fragments of P built via shuffles from C-fragments)
        #pragma unroll
        for (int kc = 0; kc < 8; kc++) {
            int src = (g << 2) | (tig >> 1);
            float x0 = __shfl_sync(0xffffffffu, s[kc][0], src);
            float x1 = __shfl_sync(0xffffffffu, s[kc][1], src);
            float x2 = __shfl_sync(0xffffffffu, s[kc][2], src);
            float x3 = __shfl_sync(0xffffffffu, s[kc][3], src);
            float z0 = __shfl_sync(0xffffffffu, s[kc][0], src + 2);
            float z1 = __shfl_sync(0xffffffffu, s[kc][1], src + 2);
            float z2 = __shfl_sync(0xffffffffu, s[kc][2], src + 2);
            float z3 = __shfl_sync(0xffffffffu, s[kc][3], src + 2);
            bool odd = (tig & 1) != 0;
            uint32_t a0 = __float_as_uint(odd ? x1 : x0);
            uint32_t a1 = __float_as_uint(odd ? x3 : x2);
            uint32_t a2 = __float_as_uint(odd ? z1 : z0);
            uint32_t a3 = __float_as_uint(odd ? z3 : z2);
            #pragma unroll
            for (int nt = 0; nt < 16; nt++) {
                uint32_t b0 = __float_as_uint(Vs[(kc * 8 + tig) * ROWP + nt * 8 + g]);
                uint32_t b1 = __float_as_uint(Vs[(kc * 8 + tig + 4) * ROWP + nt * 8 + g]);
                mma_tf32(o[nt][0], o[nt][1], o[nt][2], o[nt][3], a0, a1, a2, a3, b0, b1);
            }
        }
    }

    // epilogue: normalize, gate, tf32-round (y feeds O-proj GEMM)
    float f0 = (1.f / l0) * agate[rg0 * NH + h];
    float f1 = (1.f / l1) * agate[rg1 * NH + h];
    #pragma unroll
    for (int nt = 0; nt < 16; nt++) {
        float2 w0, w1;
        w0.x = to_tf32(o[nt][0] * f0); w0.y = to_tf32(o[nt][1] * f0);
        w1.x = to_tf32(o[nt][2] * f1); w1.y = to_tf32(o[nt][3] * f1);
        *(float2*)&y[(size_t)rg0 * DIM + h * HD + nt * 8 + 2 * tig] = w0;
        *(float2*)&y[(size_t)rg1 * DIM + h * HD + nt * 8 + 2 * tig] = w1;
    }
}

// ---------------- launch ----------------
extern "C" void kernel_launch(void* const* d_in, const int* in_sizes, int n_in,
                              void* d_out, int out_size) {
    const float* x           = (const float*)d_in[0];
    const float* ve          = (const float*)d_in[1];
    const float* qkvo_w      = (const float*)d_in[2];
    const float* attn_gate_w = (const float*)d_in[3];
    const float* ve_gate_w   = (const float*)d_in[4];
    const float* c_fc        = (const float*)d_in[5];
    const float* c_proj      = (const float*)d_in[6];
    const float* sa_lambdas  = (const float*)d_in[7];
    const float* cosb        = (const float*)d_in[8];
    const float* sinb        = (const float*)d_in[9];
    const float* attn_scale  = (const float*)d_in[10];
    const int*   docs        = (const int*)d_in[11];
    const int*   key_offset  = (const int*)d_in[12];
    float*       out         = (float*)d_out;

    float *xn, *qkv, *krot, *y, *x1, *hbuf, *agate, *vgate, *wqkv, *wfc, *wpT;
    cudaGetSymbolAddress((void**)&xn,    g_xn);
    cudaGetSymbolAddress((void**)&qkv,   g_qkv);
    cudaGetSymbolAddress((void**)&krot,  g_krot);
    cudaGetSymbolAddress((void**)&y,     g_y);
    cudaGetSymbolAddress((void**)&x1,    g_x1);
    cudaGetSymbolAddress((void**)&hbuf,  g_h);
    cudaGetSymbolAddress((void**)&agate, g_agate);
    cudaGetSymbolAddress((void**)&vgate, g_vgate);
    cudaGetSymbolAddress((void**)&wqkv,  g_wqkv);
    cudaGetSymbolAddress((void**)&wfc,   g_wfc);
    cudaGetSymbolAddress((void**)&wpT,   g_wpT);

    cudaFuncSetAttribute(flash_mma_kernel, cudaFuncAttributeMaxDynamicSharedMemorySize,
                         FL_SMEM);
    cudaFuncSetAttribute(tf32_gemm_kernel<0>, cudaFuncAttributeMaxDynamicSharedMemorySize,
                         GEMM_SMEM);
    cudaFuncSetAttribute(tf32_gemm_kernel<1>, cudaFuncAttributeMaxDynamicSharedMemorySize,
                         GEMM_SMEM);
    cudaFuncSetAttribute(tf32_gemm_kernel<2>, cudaFuncAttributeMaxDynamicSharedMemorySize,
                         GEMM_SMEM);

    // weight conversions (rounded tf32 copies; c_proj also transposed to [N,K])
    round_tf32_kernel<<<(4 * DIM * DIM / 4 + 255) / 256, 256>>>(qkvo_w, wqkv, 4 * DIM * DIM / 4);
    round_tf32_kernel<<<((size_t)FFN * DIM / 4 + 255) / 256, 256>>>(c_fc, wfc, FFN * DIM / 4);
    transpose_round_kernel<<<dim3(DIM / 32, FFN / 32), dim3(32, 8)>>>(c_proj, wpT);

    // 1. xn = round_tf32(rmsnorm(x))
    rmsnorm_kernel<<<T_SEQ, 256>>>(x, xn);
    // 2. qkv = lam0 * xn @ Wqkv^T
    tf32_gemm_kernel<0><<<dim3(3 * DIM / GBN, T_SEQ / GBM), 256, GEMM_SMEM>>>(
        xn, wqkv, qkv, nullptr, sa_lambdas, 0, 3 * DIM, DIM);
    // 3. per-head rmsnorm + rotary (tf32-rounded)
    qkrot_kernel<<<dim3(32, T_SEQ), 128>>>(qkv, krot, cosb, sinb);
    // 4. key-offset shift
    kshift_kernel<<<(T_SEQ * NH * HD) / 256, 256>>>(krot, qkv, key_offset);
    // 5. gates
    gates_kernel<<<T_SEQ, 256>>>(xn, attn_gate_w, ve_gate_w, agate, vgate);
    // 6. v update (tf32-rounded)
    vupdate_kernel<<<(T_SEQ * DIM) / 256, 256>>>(qkv, ve, vgate);
    // 7. MMA flash attention with doc-block skip
    flash_mma_kernel<<<dim3(T_SEQ / 64, NH), 128, FL_SMEM>>>(
        qkv, docs, attn_scale, agate, y);
    // 8. x1 = x + lam1 * y @ Wo^T
    tf32_gemm_kernel<2><<<dim3(DIM / GBN, T_SEQ / GBM), 256, GEMM_SMEM>>>(
        y, wqkv + (size_t)3 * DIM * DIM, x1, x, sa_lambdas, 1, DIM, DIM);
    // 9. xn = round_tf32(rmsnorm(x1))
    rmsnorm_kernel<<<T_SEQ, 256>>>(x1, xn);
    // 10. h = round_tf32(relu(xn @ c_fc^T)^2)
    tf32_gemm_kernel<1><<<dim3(FFN / GBN, T_SEQ / GBM), 256, GEMM_SMEM>>>(
        xn, wfc, hbuf, nullptr, nullptr, 0, FFN, DIM);
    // 11. out = x1 + h @ c_proj   (via c_proj^T, K=8192)
    tf32_gemm_kernel<2><<<dim3(DIM / GBN, T_SEQ / GBM), 256, GEMM_SMEM>>>(
        hbuf, wpT, out, x1, nullptr, 0, DIM, FFN);
}